// round 3
// baseline (speedup 1.0000x reference)
#include <cuda_runtime.h>
#include <math.h>

#define Bv 2
#define Lv 2048
#define Hv 16
#define DKv 64
#define DMv 1024
#define BHv (Bv*Hv)

// ---------------- scratch (static __device__ globals; no allocation) ----------
__device__ float g_Q[(size_t)BHv*Lv*DKv];
__device__ float g_K[(size_t)BHv*Lv*DKv];
__device__ float g_V[(size_t)BHv*Lv*DKv];
__device__ float g_ctx[(size_t)Bv*Lv*DMv];
__device__ float g_proj[(size_t)Bv*Lv*DMv];
// fallback attention buffer in case d_out only holds x (512 MB .bss)
__device__ float g_attn_fb[(size_t)BHv*Lv*Lv];

// ---------------- block reductions --------------------------------------------
__device__ __forceinline__ float blk_reduce_sum(float v, float* red) {
#pragma unroll
    for (int o = 16; o > 0; o >>= 1) v += __shfl_xor_sync(0xffffffffu, v, o);
    const int w = threadIdx.x >> 5;
    if ((threadIdx.x & 31) == 0) red[w] = v;
    __syncthreads();
    if (threadIdx.x < 32) {
        float t = (threadIdx.x < 8) ? red[threadIdx.x] : 0.f;
#pragma unroll
        for (int o = 4; o > 0; o >>= 1) t += __shfl_xor_sync(0xffffffffu, t, o);
        if (threadIdx.x == 0) red[0] = t;
    }
    __syncthreads();
    float r = red[0];
    __syncthreads();
    return r;
}

__device__ __forceinline__ float blk_reduce_max(float v, float* red) {
#pragma unroll
    for (int o = 16; o > 0; o >>= 1) v = fmaxf(v, __shfl_xor_sync(0xffffffffu, v, o));
    const int w = threadIdx.x >> 5;
    if ((threadIdx.x & 31) == 0) red[w] = v;
    __syncthreads();
    if (threadIdx.x < 32) {
        float t = (threadIdx.x < 8) ? red[threadIdx.x] : -INFINITY;
#pragma unroll
        for (int o = 4; o > 0; o >>= 1) t = fmaxf(t, __shfl_xor_sync(0xffffffffu, t, o));
        if (threadIdx.x == 0) red[0] = t;
    }
    __syncthreads();
    float r = red[0];
    __syncthreads();
    return r;
}

// ---------------- dense NT GEMM: C[m][n] = sum_k A[m,k]*B[n,k] ----------------
// M = 4096, N = 1024, K = 1024. 128x128 tile, 8x8 microtile, 256 threads.
// which: 0->g_Q, 1->g_K, 2->g_V (head-split layout), 3->A=g_ctx, C=g_proj (row-major)
__global__ void __launch_bounds__(256) gemm_nt128(const float* __restrict__ A,
                                                  const float* __restrict__ Bm,
                                                  int which)
{
    __shared__ float As[8][128];
    __shared__ float Bs[8][128];
    const int bm = blockIdx.y * 128;
    const int bn = blockIdx.x * 128;
    const int tid = threadIdx.x;
    const int lr = tid >> 1;
    const int lc = (tid & 1) << 2;
    const int tx = tid & 15;
    const int ty = tid >> 4;

    const float* Aeff = (which == 3) ? g_ctx : A;

    float acc[8][8];
#pragma unroll
    for (int i = 0; i < 8; ++i)
#pragma unroll
        for (int j = 0; j < 8; ++j) acc[i][j] = 0.f;

    const float* Ap = Aeff + (size_t)(bm + lr) * DMv + lc;
    const float* Bp = Bm  + (size_t)(bn + lr) * DMv + lc;

    for (int k0 = 0; k0 < DMv; k0 += 8) {
        float4 av = *(const float4*)(Ap + k0);
        float4 bv = *(const float4*)(Bp + k0);
        __syncthreads();
        As[lc+0][lr]=av.x; As[lc+1][lr]=av.y; As[lc+2][lr]=av.z; As[lc+3][lr]=av.w;
        Bs[lc+0][lr]=bv.x; Bs[lc+1][lr]=bv.y; Bs[lc+2][lr]=bv.z; Bs[lc+3][lr]=bv.w;
        __syncthreads();
#pragma unroll
        for (int kk = 0; kk < 8; ++kk) {
            float a[8], b[8];
#pragma unroll
            for (int i = 0; i < 8; ++i) a[i] = As[kk][ty*8 + i];
#pragma unroll
            for (int j = 0; j < 8; ++j) b[j] = Bs[kk][tx*8 + j];
#pragma unroll
            for (int i = 0; i < 8; ++i)
#pragma unroll
                for (int j = 0; j < 8; ++j) acc[i][j] = fmaf(a[i], b[j], acc[i][j]);
        }
    }

    float* C = (which == 0) ? g_Q : (which == 1) ? g_K : (which == 2) ? g_V : g_proj;
#pragma unroll
    for (int i = 0; i < 8; ++i) {
        const int m = bm + ty*8 + i;
#pragma unroll
        for (int j = 0; j < 8; ++j) {
            const int n = bn + tx*8 + j;
            size_t idx;
            if (which < 3) {
                const int b_ = m >> 11, l_ = m & (Lv-1);
                const int h_ = n >> 6,  d_ = n & (DKv-1);
                idx = (((size_t)(b_*Hv + h_))*Lv + l_)*DKv + d_;
            } else {
                idx = (size_t)m*DMv + n;
            }
            C[idx] = acc[i][j];
        }
    }
}

// ---------------- banded scores: S = Q K^T / 8 - bias (in-band only) ----------
__global__ void __launch_bounds__(256) scores_kernel(float* __restrict__ attn_arg,
    const float* __restrict__ scl_p, const float* __restrict__ tau_p,
    const int* __restrict__ ws_p)
{
    const int bh = blockIdx.z;
    const int q0 = blockIdx.y << 6;
    const int k0 = blockIdx.x << 6;
    const int hs = (*ws_p) >> 1;
    if (k0 > q0 + 63 + hs || k0 + 63 < q0 - hs) return;

    float* attn = attn_arg ? attn_arg : g_attn_fb;

    __shared__ float Qs[64][65];
    __shared__ float Ks[64][65];
    const int tid = threadIdx.x;
    const int r  = tid >> 2;
    const int c4 = (tid & 3) << 4;

    const float* qrow = g_Q + ((size_t)bh*Lv + q0 + r)*DKv + c4;
    const float* krow = g_K + ((size_t)bh*Lv + k0 + r)*DKv + c4;
#pragma unroll
    for (int u = 0; u < 16; u += 4) {
        float4 a = *(const float4*)(qrow + u);
        Qs[c4+u+0][r]=a.x; Qs[c4+u+1][r]=a.y; Qs[c4+u+2][r]=a.z; Qs[c4+u+3][r]=a.w;
        float4 c = *(const float4*)(krow + u);
        Ks[c4+u+0][r]=c.x; Ks[c4+u+1][r]=c.y; Ks[c4+u+2][r]=c.z; Ks[c4+u+3][r]=c.w;
    }
    __syncthreads();

    const int tx = tid & 15, ty = tid >> 4;
    float acc[4][4];
#pragma unroll
    for (int i = 0; i < 4; ++i)
#pragma unroll
        for (int j = 0; j < 4; ++j) acc[i][j] = 0.f;

#pragma unroll
    for (int kk = 0; kk < 64; ++kk) {
        float a[4], b[4];
#pragma unroll
        for (int i = 0; i < 4; ++i) a[i] = Qs[kk][(ty<<2)+i];
#pragma unroll
        for (int j = 0; j < 4; ++j) b[j] = Ks[kk][(tx<<2)+j];
#pragma unroll
        for (int i = 0; i < 4; ++i)
#pragma unroll
            for (int j = 0; j < 4; ++j) acc[i][j] = fmaf(a[i], b[j], acc[i][j]);
    }

    const float iscl = 1.f / (*scl_p);
    const float itau = 1.f / (*tau_p);
    float* base = attn + (size_t)bh*Lv*Lv;
#pragma unroll
    for (int i = 0; i < 4; ++i) {
        const int q = q0 + (ty<<2) + i;
#pragma unroll
        for (int j = 0; j < 4; ++j) {
            const int k = k0 + (tx<<2) + j;
            const int rel = q - k;
            if (rel <= hs && rel >= -hs) {
                const float bias = expf(-fabsf((float)rel * iscl) * itau);
                base[(size_t)q*Lv + k] = acc[i][j]*0.125f - bias;
            }
        }
    }
}

// ---------------- row softmax; writes full 2048-wide row (zeros outside band) --
__global__ void __launch_bounds__(256) softmax_kernel(float* __restrict__ attn_arg,
    const float* __restrict__ mask, const float* __restrict__ scl_p,
    const float* __restrict__ tau_p, const int* __restrict__ ws_p)
{
    const int q  = blockIdx.x;
    const int bh = blockIdx.y;
    const int b  = bh >> 4;
    const int tid = threadIdx.x;
    __shared__ float buf[Lv];
    __shared__ float red[32];

    float* attn = attn_arg ? attn_arg : g_attn_fb;
    const int hs = (*ws_p) >> 1;
    const float mval = mask[b*Lv + q];
    float* row = attn + ((size_t)bh*Lv + q)*Lv;

    int lo, hi;
    if (mval != 0.f) {
        lo = q - hs; if (lo < 0) lo = 0;
        hi = q + hs; if (hi > Lv-1) hi = Lv-1;
        for (int c = lo + tid; c <= hi; c += 256) buf[c - lo] = row[c];
    } else {
        // whole row is NEG - bias: softmax reduces to softmax(-bias) over all L
        lo = 0; hi = Lv-1;
        const float iscl = 1.f / (*scl_p);
        const float itau = 1.f / (*tau_p);
        for (int c = tid; c < Lv; c += 256)
            buf[c] = -expf(-fabsf((float)(q - c) * iscl) * itau);
    }
    __syncthreads();

    const int n = hi - lo + 1;
    float mx = -INFINITY;
    for (int i = tid; i < n; i += 256) mx = fmaxf(mx, buf[i]);
    mx = blk_reduce_max(mx, red);

    float s = 0.f;
    for (int i = tid; i < n; i += 256) { float e = expf(buf[i] - mx); buf[i] = e; s += e; }
    s = blk_reduce_sum(s, red);
    const float inv = 1.f / s;
    __syncthreads();

    for (int c = tid; c < Lv; c += 256) {
        float v = 0.f;
        if (c >= lo && c <= hi) v = buf[c - lo] * inv;
        row[c] = v;
    }
}

// ---------------- ctx = attn @ V (band-skip when tile fully unmasked) ---------
__global__ void __launch_bounds__(256) av_kernel(const float* __restrict__ attn_arg,
    const float* __restrict__ mask, const int* __restrict__ ws_p)
{
    const int q0 = blockIdx.x << 6;
    const int bh = blockIdx.y;
    const int b = bh >> 4, h = bh & 15;
    const int hs = (*ws_p) >> 1;
    const int tid = threadIdx.x;

    const float* attn = attn_arg ? attn_arg : g_attn_fb;

    __shared__ float Ps[64][65];   // [m][q]
    __shared__ float Vs[64][65];   // [m][d]
    __shared__ int s_all;
    if (tid == 0) s_all = 1;
    __syncthreads();
    if (tid < 64 && mask[b*Lv + q0 + tid] == 0.f) s_all = 0;
    __syncthreads();
    const int allm = s_all;

    const int r  = tid >> 2, c4 = (tid & 3) << 4;
    const int tx = tid & 15, ty = tid >> 4;
    float acc[4][4];
#pragma unroll
    for (int i = 0; i < 4; ++i)
#pragma unroll
        for (int j = 0; j < 4; ++j) acc[i][j] = 0.f;

    const float* abase = attn + (size_t)bh*Lv*Lv;
    for (int m0 = 0; m0 < Lv; m0 += 64) {
        // out-of-band attention probabilities are exactly 0 (safe to skip),
        // except masked rows where the full row is nonzero
        if (allm && (m0 > q0 + 63 + hs || m0 + 63 < q0 - hs)) continue;
        __syncthreads();
        const float* arow = abase + (size_t)(q0 + r)*Lv + m0 + c4;
#pragma unroll
        for (int u = 0; u < 16; u += 4) {
            float4 a = *(const float4*)(arow + u);
            Ps[c4+u+0][r]=a.x; Ps[c4+u+1][r]=a.y; Ps[c4+u+2][r]=a.z; Ps[c4+u+3][r]=a.w;
        }
        const float* vrow = g_V + ((size_t)bh*Lv + m0 + r)*DKv + c4;
#pragma unroll
        for (int u = 0; u < 16; u += 4) {
            float4 a = *(const float4*)(vrow + u);
            Vs[r][c4+u+0]=a.x; Vs[r][c4+u+1]=a.y; Vs[r][c4+u+2]=a.z; Vs[r][c4+u+3]=a.w;
        }
        __syncthreads();
#pragma unroll
        for (int kk = 0; kk < 64; ++kk) {
            float a[4], bb[4];
#pragma unroll
            for (int i = 0; i < 4; ++i) a[i] = Ps[kk][(ty<<2)+i];
#pragma unroll
            for (int j = 0; j < 4; ++j) bb[j] = Vs[kk][(tx<<2)+j];
#pragma unroll
            for (int i = 0; i < 4; ++i)
#pragma unroll
                for (int j = 0; j < 4; ++j) acc[i][j] = fmaf(a[i], bb[j], acc[i][j]);
        }
    }

#pragma unroll
    for (int i = 0; i < 4; ++i) {
        const int qq = q0 + (ty<<2) + i;
#pragma unroll
        for (int j = 0; j < 4; ++j) {
            const int d = (tx<<2) + j;
            g_ctx[((size_t)b*Lv + qq)*DMv + h*DKv + d] = acc[i][j];
        }
    }
}

// ---------------- residual + LayerNorm ----------------------------------------
__global__ void __launch_bounds__(256) ln_kernel(const float* __restrict__ qin,
    const float* __restrict__ lnw, const float* __restrict__ lnb,
    float* __restrict__ out)
{
    const int m = blockIdx.x;
    const int tid = threadIdx.x;
    __shared__ float xs[DMv];
    __shared__ float red[32];

    float s = 0.f;
    for (int i = tid; i < DMv; i += 256) {
        float v = g_proj[(size_t)m*DMv + i] + qin[(size_t)m*DMv + i];
        xs[i] = v; s += v;
    }
    s = blk_reduce_sum(s, red);
    const float mean = s * (1.f/DMv);

    float vs = 0.f;
    for (int i = tid; i < DMv; i += 256) { float d = xs[i] - mean; vs += d*d; }
    vs = blk_reduce_sum(vs, red);
    const float inv = rsqrtf(vs * (1.f/DMv) + 1e-6f);

    for (int i = tid; i < DMv; i += 256)
        out[(size_t)m*DMv + i] = (xs[i] - mean) * inv * lnw[i] + lnb[i];
}

// ---------------- launcher ------------------------------------------------------
extern "C" void kernel_launch(void* const* d_in, const int* in_sizes, int n_in,
                              void* d_out, int out_size)
{
    const float* q    = (const float*)d_in[0];
    const float* k    = (const float*)d_in[1];
    const float* v    = (const float*)d_in[2];
    const float* mask = (const float*)d_in[3];
    const float* Wq   = (const float*)d_in[4];
    const float* Wk   = (const float*)d_in[5];
    const float* Wv   = (const float*)d_in[6];
    const float* Wo   = (const float*)d_in[7];
    const float* scl  = (const float*)d_in[8];
    const float* tau  = (const float*)d_in[9];
    const float* lnw  = (const float*)d_in[10];
    const float* lnb  = (const float*)d_in[11];
    const int*   ws   = (const int*)d_in[12];   // int64 LE low word also reads OK
    (void)in_sizes; (void)n_in;

    float* xout = (float*)d_out;
    const long long XN = (long long)Bv*Lv*DMv;            // 4,194,304
    const long long AN = (long long)BHv*Lv*Lv;            // 134,217,728
    // attention goes into d_out right after x if there is room; else static fallback
    float* attn_out = ((long long)out_size >= XN + AN) ? (xout + XN) : nullptr;

    const dim3 gg(DMv/128, (Bv*Lv)/128);                  // (8, 32)

    gemm_nt128<<<gg, 256>>>(q, Wq, 0);
    gemm_nt128<<<gg, 256>>>(k, Wk, 1);
    gemm_nt128<<<gg, 256>>>(v, Wv, 2);

    scores_kernel<<<dim3(Lv/64, Lv/64, BHv), 256>>>(attn_out, scl, tau, ws);
    softmax_kernel<<<dim3(Lv, BHv), 256>>>(attn_out, mask, scl, tau, ws);
    av_kernel<<<dim3(Lv/64, BHv), 256>>>(attn_out, mask, ws);

    gemm_nt128<<<gg, 256>>>(nullptr, Wo, 3);              // A = g_ctx internally
    ln_kernel<<<Bv*Lv, 256>>>(q, lnw, lnb, xout);
}